// round 16
// baseline (speedup 1.0000x reference)
#include <cuda_runtime.h>
#include <cuda_bf16.h>
#include <cuda_fp16.h>
#include <cstdint>

// ===================== scratch (device globals; no allocation allowed) ======
// 32K-PERMUTED fp16 STORAGE: X and WT store every aligned 32-value k-group
// with fp16-pair p placed at word position 4*(p&3)+(p>>2). Thread tg's mma
// fragments for BOTH k16 sub-steps (pairs tg, tg+4, tg+8, tg+12) are then the
// 4 consecutive words 4tg..4tg+3 -> one LDS.128 per row.
#define MAXN 20000
#define MAXE 400000
__device__ __nv_bfloat16 g_Hb[(size_t)MAXN * 1280];  // GEMM out (bf16, dis-scaled)
__device__ __half g_X[(size_t)MAXN * 1280];   // GEMM input (fp16, k-permuted)
__device__ float  g_A[(size_t)MAXN * 320];    // layer-3 gather out (fp32)
__device__ __half g_WT1[1280 * 1280];
__device__ __half g_WT2[640 * 1280];
__device__ __half g_WT3[320 * 640];
__device__ float g_dis[MAXN];
__device__ int   g_deg[MAXN];
__device__ int   g_rowptr[MAXN + 1];
__device__ int   g_cursor[MAXN];
__device__ int   g_col[MAXE];

// ===================== helpers =====================
__device__ __forceinline__ void mma_f16(float* d, const uint32_t* a, const uint32_t* b) {
    asm volatile(
        "mma.sync.aligned.m16n8k16.row.col.f32.f16.f16.f32 "
        "{%0,%1,%2,%3}, {%4,%5,%6,%7}, {%8,%9}, {%0,%1,%2,%3};\n"
        : "+f"(d[0]), "+f"(d[1]), "+f"(d[2]), "+f"(d[3])
        : "r"(a[0]), "r"(a[1]), "r"(a[2]), "r"(a[3]), "r"(b[0]), "r"(b[1]));
}
__device__ __forceinline__ uint32_t smem_u32(const void* p) {
    uint32_t a;
    asm("{ .reg .u64 t; cvta.to.shared.u64 t, %1; cvt.u32.u64 %0, t; }" : "=r"(a) : "l"(p));
    return a;
}

// ===================== degree / normalization =====================
__global__ void k_init_deg(int* deg, int n) {
    int i = blockIdx.x * blockDim.x + threadIdx.x;
    if (i < n) deg[i] = 1;
}
__global__ void k_count_deg(const int* __restrict__ dst, int* deg, int e) {
    int i = blockIdx.x * blockDim.x + threadIdx.x;
    if (i < e) atomicAdd(&deg[dst[i]], 1);
}

// ===================== CSR build =====================
#define SCHUNK 20
__global__ void __launch_bounds__(1024)
k_scan(const int* __restrict__ deg, int* __restrict__ rowptr,
       int* __restrict__ cursor, float* __restrict__ dis, int n) {
    __shared__ int warpsum[32];
    const int tid = threadIdx.x;
    const int lane = tid & 31, wid = tid >> 5;
    const int chunk = (n + 1023) / 1024;
    const int start = tid * chunk;
    const int end = (start + chunk < n) ? start + chunk : n;
    const bool full20 = (chunk == SCHUNK) && (start + SCHUNK <= n);
    int dcache[SCHUNK];
    int cnt = end > start ? end - start : 0;
    if (full20) {
        const int4* dp = (const int4*)(deg + start);
#pragma unroll
        for (int q = 0; q < 5; q++) {
            int4 v4 = dp[q];
            dcache[q * 4 + 0] = v4.x;
            dcache[q * 4 + 1] = v4.y;
            dcache[q * 4 + 2] = v4.z;
            dcache[q * 4 + 3] = v4.w;
        }
        cnt = SCHUNK;
    } else {
        for (int i = 0; i < cnt; i++) dcache[i] = deg[start + i];
    }
    int s = 0;
    for (int i = 0; i < cnt; i++) s += dcache[i];
    int v = s;
#pragma unroll
    for (int o = 1; o < 32; o <<= 1) {
        int u = __shfl_up_sync(0xFFFFFFFFu, v, o);
        if (lane >= o) v += u;
    }
    if (lane == 31) warpsum[wid] = v;
    __syncthreads();
    if (wid == 0) {
        int w = warpsum[lane];
#pragma unroll
        for (int o = 1; o < 32; o <<= 1) {
            int u = __shfl_up_sync(0xFFFFFFFFu, w, o);
            if (lane >= o) w += u;
        }
        warpsum[lane] = w;
    }
    __syncthreads();
    int incl = v + (wid ? warpsum[wid - 1] : 0);
    int run = incl - s;
    int rp[SCHUNK];
    float dd[SCHUNK];
    for (int i = 0; i < cnt; i++) {
        rp[i] = run;
        dd[i] = rsqrtf((float)dcache[i]);
        run += dcache[i];
    }
    if (full20) {
        int4* rpp = (int4*)(rowptr + start);
        int4* cup = (int4*)(cursor + start);
        float4* dip = (float4*)(dis + start);
#pragma unroll
        for (int q = 0; q < 5; q++) {
            int4 rv = make_int4(rp[q * 4], rp[q * 4 + 1], rp[q * 4 + 2], rp[q * 4 + 3]);
            rpp[q] = rv;
            cup[q] = rv;
            dip[q] = make_float4(dd[q * 4], dd[q * 4 + 1], dd[q * 4 + 2], dd[q * 4 + 3]);
        }
    } else {
        for (int i = 0; i < cnt; i++) {
            rowptr[start + i] = rp[i];
            cursor[start + i] = rp[i];
            dis[start + i] = dd[i];
        }
    }
    if (start < n && end == n) rowptr[n] = run;
}

__global__ void k_fill(const int* __restrict__ src, const int* __restrict__ dst,
                       int* cursor, int* __restrict__ col, int e, int n) {
    int i = blockIdx.x * blockDim.x + threadIdx.x;
    if (i < e) {
        int pos = atomicAdd(&cursor[dst[i]], 1);
        col[pos] = src[i];
    } else if (i < e + n) {
        int j = i - e;
        int pos = atomicAdd(&cursor[j], 1);
        col[pos] = j;
    }
}

// ===================== conversions (32k-permuted fp16 output) ===============
// Per 32-value group: word position 4*(p&3)+(p>>2) holds pair p (p=0..15).
// Thread i handles one 32-group.
__global__ void k_f2h(const float* __restrict__ in, __half* __restrict__ out, size_t n32) {
    size_t i = (size_t)blockIdx.x * blockDim.x + threadIdx.x;
    if (i < n32) {
        const float* ip = in + i * 32;
        float f[32];
#pragma unroll
        for (int q = 0; q < 8; q++) {
            float4 v = *(const float4*)(ip + q * 4);
            f[q * 4] = v.x; f[q * 4 + 1] = v.y; f[q * 4 + 2] = v.z; f[q * 4 + 3] = v.w;
        }
        uint32_t w[16];
#pragma unroll
        for (int p = 0; p < 16; p++) {
            __half2 h = __floats2half2_rn(f[2 * p], f[2 * p + 1]);
            w[4 * (p & 3) + (p >> 2)] = *(uint32_t*)&h;
        }
        uint4* op = (uint4*)(out + i * 32);
#pragma unroll
        for (int q = 0; q < 4; q++)
            op[q] = make_uint4(w[q * 4], w[q * 4 + 1], w[q * 4 + 2], w[q * 4 + 3]);
    }
}

// WT[m][kperm] = fp16(W[k][m]); pairs permuted within 32-k groups.
// k0 = blockIdx.y*32 is 32-aligned, so tx (0..31) spans exactly one group.
__global__ void k_wt(const float* __restrict__ W, __half* __restrict__ WT,
                     int K, int M) {
    __shared__ float t[32][33];
    int k0 = blockIdx.y * 32, m0 = blockIdx.x * 32;
    int tx = threadIdx.x, ty = threadIdx.y;
#pragma unroll
    for (int i = ty; i < 32; i += 8)
        t[i][tx] = W[(size_t)(k0 + i) * M + m0 + tx];
    __syncthreads();
    int p = tx >> 1, j = tx & 1;
    int pos = 4 * (p & 3) + (p >> 2);
    int pk = pos * 2 + j;
#pragma unroll
    for (int i = ty; i < 32; i += 8)
        WT[(size_t)(m0 + i) * K + k0 + pk] = __float2half_rn(t[tx][i]);
}

// ===================== fp16 tensor-core GEMM (cp.async, 5-stage) ============
// Hb[N, M] = bf16( (Ah[N,K] @ WT[M,K]^T) * dis[row] )   fp32 accumulate
// Block 128x128, BK=32, 8 warps (2x4), warp tile 64x32, mma m16n8k16.
// SMEM rows: exactly 16 words (32 fp16); LDS.128 fragment loads are
// conflict-free with this unpadded layout (addr mod 32 = 16*(g4&1)+4*tg).
#define GW 16
#define AW (128 * GW)
#define STAGE_WORDS (AW * 2)
#define NSTAGE 5

__global__ void __launch_bounds__(256, 2)
k_gemm_h(const __half* __restrict__ Ah, const __half* __restrict__ WT,
         __nv_bfloat16* __restrict__ C, const float* __restrict__ dis,
         int N, int K, int M) {
    extern __shared__ uint32_t smem[];
    const uint32_t sbase0 = smem_u32(smem);
    const int tid = threadIdx.x;
    const int wid = tid >> 5;
    const int lid = tid & 31;
    const int g4  = lid >> 2;
    const int tg  = lid & 3;
    const int wm  = wid >> 2;
    const int wn  = wid & 3;
    const int row0 = blockIdx.y * 128;
    const int col0 = blockIdx.x * 128;
    const int nk = K >> 5;             // BK = 32

    float acc[4][4][4];
#pragma unroll
    for (int i = 0; i < 4; i++)
#pragma unroll
        for (int j = 0; j < 4; j++)
#pragma unroll
            for (int k = 0; k < 4; k++) acc[i][j][k] = 0.0f;

    auto load_stage = [&](int s, int kt) {
        const int k0 = kt << 5;
        const uint32_t sb = sbase0 + (uint32_t)s * STAGE_WORDS * 4;
        // A: 128 rows x 32 fp16 (64B) = 512 x 16B chunks; 2 per thread
#pragma unroll
        for (int i = 0; i < 2; i++) {
            int c = tid + i * 256;
            int row = c >> 2, off = c & 3;
            int gr = row0 + row;
            int grc = gr < N ? gr : N - 1;
            const __half* src = Ah + (size_t)grc * K + k0 + off * 8;
            uint32_t dst = sb + (uint32_t)(row * GW + off * 4) * 4;
            int sz = (gr < N) ? 16 : 0;
            asm volatile("cp.async.cg.shared.global [%0], [%1], 16, %2;"
                         :: "r"(dst), "l"(src), "r"(sz));
        }
        // B: 128 n-rows x 32 fp16
#pragma unroll
        for (int i = 0; i < 2; i++) {
            int c = tid + i * 256;
            int n = c >> 2, off = c & 3;
            int gc = col0 + n;
            int gcc = gc < M ? gc : M - 1;
            const __half* src = WT + (size_t)gcc * K + k0 + off * 8;
            uint32_t dst = sb + (uint32_t)(AW + n * GW + off * 4) * 4;
            int sz = (gc < M) ? 16 : 0;
            asm volatile("cp.async.cg.shared.global [%0], [%1], 16, %2;"
                         :: "r"(dst), "l"(src), "r"(sz));
        }
        asm volatile("cp.async.commit_group;" ::: "memory");
    };

    for (int s = 0; s < NSTAGE - 1 && s < nk; s++) load_stage(s, s);

    for (int t = 0; t < nk; t++) {
        if (t + NSTAGE - 1 <= nk)
            asm volatile("cp.async.wait_group %0;" :: "n"(NSTAGE - 2) : "memory");
        else
            asm volatile("cp.async.wait_group 0;" ::: "memory");
        __syncthreads();
        if (t + NSTAGE - 1 < nk) load_stage((t + NSTAGE - 1) % NSTAGE, t + NSTAGE - 1);

        const uint32_t* as = smem + ((t % NSTAGE) * STAGE_WORDS);
        const uint32_t* bs = as + AW;

        // One LDS.128 per row serves BOTH k16 sub-steps:
        // words 4tg..4tg+3 = pairs (tg, tg+4, tg+8, tg+12)
        uint4 aF[4][2];   // [mi][row r / r+8]
        uint4 bF[4];      // [nf]
#pragma unroll
        for (int mi = 0; mi < 4; mi++) {
            int r = wm * 64 + mi * 16 + g4;
            aF[mi][0] = *(const uint4*)(as + r * GW + tg * 4);
            aF[mi][1] = *(const uint4*)(as + (r + 8) * GW + tg * 4);
        }
#pragma unroll
        for (int nf = 0; nf < 4; nf++) {
            int cc = wn * 32 + nf * 8 + g4;
            bF[nf] = *(const uint4*)(bs + cc * GW + tg * 4);
        }
        // s = 0: pairs tg, tg+4 -> words .x, .y
#pragma unroll
        for (int mi = 0; mi < 4; mi++) {
            uint32_t af[4] = {aF[mi][0].x, aF[mi][1].x, aF[mi][0].y, aF[mi][1].y};
#pragma unroll
            for (int nf = 0; nf < 4; nf++) {
                uint32_t bf[2] = {bF[nf].x, bF[nf].y};
                mma_f16(acc[mi][nf], af, bf);
            }
        }
        // s = 1: pairs tg+8, tg+12 -> words .z, .w
#pragma unroll
        for (int mi = 0; mi < 4; mi++) {
            uint32_t af[4] = {aF[mi][0].z, aF[mi][1].z, aF[mi][0].w, aF[mi][1].w};
#pragma unroll
            for (int nf = 0; nf < 4; nf++) {
                uint32_t bf[2] = {bF[nf].z, bF[nf].w};
                mma_f16(acc[mi][nf], af, bf);
            }
        }
    }

    // epilogue: scale rows by dis[row], store bf16x2
#pragma unroll
    for (int mi = 0; mi < 4; mi++) {
        int r0 = row0 + wm * 64 + mi * 16 + g4;
        float d0 = (r0 < N) ? dis[r0] : 0.f;
        float d1 = (r0 + 8 < N) ? dis[r0 + 8] : 0.f;
#pragma unroll
        for (int nf = 0; nf < 4; nf++) {
            int cc = col0 + wn * 32 + nf * 8 + tg * 2;
            if (cc < M) {
                if (r0 < N)
                    *(__nv_bfloat162*)(C + (size_t)r0 * M + cc) =
                        __floats2bfloat162_rn(acc[mi][nf][0] * d0, acc[mi][nf][1] * d0);
                if (r0 + 8 < N)
                    *(__nv_bfloat162*)(C + (size_t)(r0 + 8) * M + cc) =
                        __floats2bfloat162_rn(acc[mi][nf][2] * d1, acc[mi][nf][3] * d1);
            }
        }
    }
}

// ===================== CSR gather (bf16 x8, 4-edge unroll) ===================
// outh!=null: store fp16 32K-PERMUTED (next GEMM input); else fp32 to outf.
__global__ void k_gather8(const __nv_bfloat16* __restrict__ H,
                          __half* __restrict__ outh, float* __restrict__ outf,
                          const int* __restrict__ rowptr, const int* __restrict__ col,
                          const float* __restrict__ dis, const float* __restrict__ b,
                          int M) {
    const int d = blockIdx.x;
    const int t = threadIdx.x;
    float acc[8];
#pragma unroll
    for (int i = 0; i < 8; i++) acc[i] = 0.f;
    const int beg = rowptr[d];
    const int end = rowptr[d + 1];
    int j = beg;
    for (; j + 3 < end; j += 4) {
        const int s0 = __ldg(&col[j]);
        const int s1 = __ldg(&col[j + 1]);
        const int s2 = __ldg(&col[j + 2]);
        const int s3 = __ldg(&col[j + 3]);
        uint4 u0 = __ldg((const uint4*)(H + (size_t)s0 * M) + t);
        uint4 u1 = __ldg((const uint4*)(H + (size_t)s1 * M) + t);
        uint4 u2 = __ldg((const uint4*)(H + (size_t)s2 * M) + t);
        uint4 u3 = __ldg((const uint4*)(H + (size_t)s3 * M) + t);
        const uint32_t* p0 = &u0.x;
        const uint32_t* p1 = &u1.x;
        const uint32_t* p2 = &u2.x;
        const uint32_t* p3 = &u3.x;
#pragma unroll
        for (int q = 0; q < 4; q++) {
            float2 f0 = __bfloat1622float2(*(const __nv_bfloat162*)&p0[q]);
            float2 f1 = __bfloat1622float2(*(const __nv_bfloat162*)&p1[q]);
            float2 f2 = __bfloat1622float2(*(const __nv_bfloat162*)&p2[q]);
            float2 f3 = __bfloat1622float2(*(const __nv_bfloat162*)&p3[q]);
            acc[q * 2]     += (f0.x + f1.x) + (f2.x + f3.x);
            acc[q * 2 + 1] += (f0.y + f1.y) + (f2.y + f3.y);
        }
    }
    for (; j < end; j++) {
        const int s0 = __ldg(&col[j]);
        uint4 u0 = __ldg((const uint4*)(H + (size_t)s0 * M) + t);
        const uint32_t* p0 = &u0.x;
#pragma unroll
        for (int q = 0; q < 4; q++) {
            float2 f0 = __bfloat1622float2(*(const __nv_bfloat162*)&p0[q]);
            acc[q * 2]     += f0.x;
            acc[q * 2 + 1] += f0.y;
        }
    }
    const float wd = dis[d];
    float4 b0 = __ldg((const float4*)(b) + t * 2);
    float4 b1 = __ldg((const float4*)(b) + t * 2 + 1);
    float r[8];
    r[0] = fmaxf(acc[0] * wd + b0.x, 0.f);
    r[1] = fmaxf(acc[1] * wd + b0.y, 0.f);
    r[2] = fmaxf(acc[2] * wd + b0.z, 0.f);
    r[3] = fmaxf(acc[3] * wd + b0.w, 0.f);
    r[4] = fmaxf(acc[4] * wd + b1.x, 0.f);
    r[5] = fmaxf(acc[5] * wd + b1.y, 0.f);
    r[6] = fmaxf(acc[6] * wd + b1.z, 0.f);
    r[7] = fmaxf(acc[7] * wd + b1.w, 0.f);
    if (outh) {
        // thread covers global pairs 4t..4t+3 = local pairs 4s..4s+3 of
        // 32-group g, where g = t>>2, s = t&3. Pair p -> word 4*(p&3)+(p>>2):
        // p = 4s+i -> word 4i+s.
        uint32_t* og = (uint32_t*)(outh + (size_t)d * M + (t >> 2) * 32);
        int s = t & 3;
#pragma unroll
        for (int i = 0; i < 4; i++) {
            __half2 h = __floats2half2_rn(r[2 * i], r[2 * i + 1]);
            og[4 * i + s] = *(uint32_t*)&h;
        }
    } else {
        float4* od = (float4*)(outf + (size_t)d * M) + t * 2;
        od[0] = make_float4(r[0], r[1], r[2], r[3]);
        od[1] = make_float4(r[4], r[5], r[6], r[7]);
    }
}

// ===================== fused mean-pool + MLP head ===========================
__global__ void __launch_bounds__(512)
k_head(const float* __restrict__ A, const int* __restrict__ batch,
       const float* __restrict__ fp_x,
       const float* __restrict__ Wg1, const float* __restrict__ bg1,
       const float* __restrict__ Wg2, const float* __restrict__ bg2,
       const float* __restrict__ Wf1, const float* __restrict__ bf1,
       const float* __restrict__ Wf2, const float* __restrict__ bf2,
       const float* __restrict__ Wo, const float* __restrict__ bo,
       float* __restrict__ out, int N) {
    __shared__ float xt[320];
    __shared__ float mc[193];
    __shared__ float m1[1024];
    __shared__ float m3[1024];
    __shared__ float m4[512];
    __shared__ float p2[4][128];
    __shared__ float red[16];
    const int g = blockIdx.x;
    const int tid = threadIdx.x;

    int lo = 0, hi = N;
    while (lo < hi) { int mid = (lo + hi) >> 1; if (batch[mid] < g) lo = mid + 1; else hi = mid; }
    const int beg = lo;
    hi = N;
    while (lo < hi) { int mid = (lo + hi) >> 1; if (batch[mid] < g + 1) lo = mid + 1; else hi = mid; }
    const int end = lo;
    if (tid < 320) {
        float s = 0.f;
        for (int i = beg; i < end; i++) s += A[(size_t)i * 320 + tid];
        xt[tid] = s / fmaxf((float)(end - beg), 1.0f);
    }
    __syncthreads();

    for (int m = tid; m < 1024; m += 512) {
        float acc = bg1[m];
        for (int k = 0; k < 320; k++) acc += xt[k] * Wg1[(size_t)k * 1024 + m];
        m1[m] = fmaxf(acc, 0.f);
    }
    __syncthreads();

    {
        int m = tid & 127, q = tid >> 7;
        float acc = 0.f;
        for (int k = q * 256; k < (q + 1) * 256; k++) acc += m1[k] * Wg2[(size_t)k * 128 + m];
        p2[q][m] = acc;
    }
    __syncthreads();
    if (tid < 128) mc[65 + tid] = bg2[tid] + p2[0][tid] + p2[1][tid] + p2[2][tid] + p2[3][tid];
    else if (tid < 128 + 65) mc[tid - 128] = fp_x[g * 65 + (tid - 128)];
    __syncthreads();

    for (int m = tid; m < 1024; m += 512) {
        float acc = bf1[m];
        for (int k = 0; k < 193; k++) acc += mc[k] * Wf1[(size_t)k * 1024 + m];
        m3[m] = fmaxf(acc, 0.f);
    }
    __syncthreads();

    {
        float acc = bf2[tid];
        for (int k = 0; k < 1024; k++) acc += m3[k] * Wf2[(size_t)k * 512 + tid];
        m4[tid] = fmaxf(acc, 0.f);
    }
    __syncthreads();

    float acc = m4[tid] * Wo[tid];
#pragma unroll
    for (int o = 16; o; o >>= 1) acc += __shfl_down_sync(0xFFFFFFFFu, acc, o);
    if ((tid & 31) == 0) red[tid >> 5] = acc;
    __syncthreads();
    if (tid < 16) {
        float v = red[tid];
#pragma unroll
        for (int o = 8; o; o >>= 1) v += __shfl_down_sync(0xFFFFu, v, o);
        if (tid == 0) out[g] = v + bo[0];
    }
}

// ===================== launch =====================
extern "C" void kernel_launch(void* const* d_in, const int* in_sizes, int n_in,
                              void* d_out, int out_size) {
    const float* x     = (const float*)d_in[0];
    const int*   ei    = (const int*)d_in[1];
    const int*   batch = (const int*)d_in[2];
    const float* fp_x  = (const float*)d_in[3];
    const float* W1 = (const float*)d_in[4];   const float* b1 = (const float*)d_in[5];
    const float* W2 = (const float*)d_in[6];   const float* b2 = (const float*)d_in[7];
    const float* W3 = (const float*)d_in[8];   const float* b3 = (const float*)d_in[9];
    const float* Wg1 = (const float*)d_in[10]; const float* bg1 = (const float*)d_in[11];
    const float* Wg2 = (const float*)d_in[12]; const float* bg2 = (const float*)d_in[13];
    const float* Wf1 = (const float*)d_in[14]; const float* bf1 = (const float*)d_in[15];
    const float* Wf2 = (const float*)d_in[16]; const float* bf2 = (const float*)d_in[17];
    const float* Wo  = (const float*)d_in[18]; const float* bo  = (const float*)d_in[19];

    const int N = in_sizes[0] / 1280;
    const int E = in_sizes[1] / 2;
    const int G = in_sizes[3] / 65;
    const int* srcp = ei;
    const int* dstp = ei + E;

    float *pA, *pdis;
    __half *pX, *pWT1, *pWT2, *pWT3;
    __nv_bfloat16* pHb;
    int *pdeg, *prowptr, *pcursor, *pcol;
    cudaGetSymbolAddress((void**)&pHb, g_Hb);
    cudaGetSymbolAddress((void**)&pX, g_X);
    cudaGetSymbolAddress((void**)&pA, g_A);
    cudaGetSymbolAddress((void**)&pWT1, g_WT1);
    cudaGetSymbolAddress((void**)&pWT2, g_WT2);
    cudaGetSymbolAddress((void**)&pWT3, g_WT3);
    cudaGetSymbolAddress((void**)&pdis, g_dis);
    cudaGetSymbolAddress((void**)&pdeg, g_deg);
    cudaGetSymbolAddress((void**)&prowptr, g_rowptr);
    cudaGetSymbolAddress((void**)&pcursor, g_cursor);
    cudaGetSymbolAddress((void**)&pcol, g_col);

    cudaFuncSetAttribute(k_gemm_h, cudaFuncAttributeMaxDynamicSharedMemorySize,
                         NSTAGE * STAGE_WORDS * 4);

    // side stream for CSR build (fork/join; capture-legal)
    cudaStream_t s1;
    cudaStreamCreateWithFlags(&s1, cudaStreamNonBlocking);
    cudaEvent_t evFork, evDis, evCsr;
    cudaEventCreateWithFlags(&evFork, cudaEventDisableTiming);
    cudaEventCreateWithFlags(&evDis, cudaEventDisableTiming);
    cudaEventCreateWithFlags(&evCsr, cudaEventDisableTiming);

    cudaEventRecord(evFork, 0);
    cudaStreamWaitEvent(s1, evFork, 0);

    // s1: CSR build; dis ready after k_scan; col/WT2/WT3 finish under GEMM1
    k_init_deg<<<(N + 255) / 256, 256, 0, s1>>>(pdeg, N);
    k_count_deg<<<(E + 255) / 256, 256, 0, s1>>>(dstp, pdeg, E);
    k_scan<<<1, 1024, 0, s1>>>(pdeg, prowptr, pcursor, pdis, N);
    cudaEventRecord(evDis, s1);
    k_fill<<<(E + N + 255) / 256, 256, 0, s1>>>(srcp, dstp, pcursor, pcol, E, N);
    {
        dim3 bt(32, 8);
        k_wt<<<dim3(640 / 32, 1280 / 32), bt, 0, s1>>>(W2, pWT2, 1280, 640);
        k_wt<<<dim3(320 / 32, 640 / 32), bt, 0, s1>>>(W3, pWT3, 640, 320);
    }
    cudaEventRecord(evCsr, s1);

    // default: conversions needed for GEMM1
    {
        size_t n32 = (size_t)N * 1280 / 32;
        k_f2h<<<(unsigned)((n32 + 255) / 256), 256>>>(x, pX, n32);
        dim3 bt(32, 8);
        k_wt<<<dim3(1280 / 32, 1280 / 32), bt>>>(W1, pWT1, 1280, 1280);
    }

    const unsigned smem_bytes = NSTAGE * STAGE_WORDS * 4;
    auto gemm = [&](const __half* in, const __half* WT, int K, int M) {
        dim3 gg((M + 127) / 128, (N + 127) / 128);
        k_gemm_h<<<gg, 256, smem_bytes>>>(in, WT, pHb, pdis, N, K, M);
    };

    // layer 1 (GEMM1 needs dis; gather needs full CSR)
    cudaStreamWaitEvent(0, evDis, 0);
    gemm(pX, pWT1, 1280, 1280);
    cudaStreamWaitEvent(0, evCsr, 0);
    k_gather8<<<N, 160>>>(pHb, pX, nullptr, prowptr, pcol, pdis, b1, 1280);
    // layer 2
    gemm(pX, pWT2, 1280, 640);
    k_gather8<<<N, 80>>>(pHb, pX, nullptr, prowptr, pcol, pdis, b2, 640);
    // layer 3
    gemm(pX, pWT3, 640, 320);
    k_gather8<<<N, 40>>>(pHb, nullptr, pA, prowptr, pcol, pdis, b3, 320);

    // fused mean-pool + MLP head
    k_head<<<G, 512>>>(pA, batch, fp_x, Wg1, bg1, Wg2, bg2,
                       Wf1, bf1, Wf2, bf2, Wo, bo, (float*)d_out, N);

    cudaEventDestroy(evFork);
    cudaEventDestroy(evDis);
    cudaEventDestroy(evCsr);
    cudaStreamDestroy(s1);
}

// round 17
// speedup vs baseline: 1.0506x; 1.0506x over previous
#include <cuda_runtime.h>
#include <cuda_bf16.h>
#include <cuda_fp16.h>
#include <cstdint>

// ===================== scratch (device globals; no allocation allowed) ======
// K-PERMUTED fp16 STORAGE: X and WT store every aligned 16-value k-group with
// fp16-PAIRS reordered [0,4,1,5,2,6,3,7], so the m16n8k16 fragment pairs
// (k=2tg..2tg+1, k=2tg+8..2tg+9) are adjacent -> one LDS.64 per row fragment.
#define MAXN 20000
#define MAXE 400000
__device__ __nv_bfloat16 g_Hb[(size_t)MAXN * 1280];  // GEMM out (bf16, dis-scaled)
__device__ __half g_X[(size_t)MAXN * 1280];   // GEMM input (fp16, k-permuted)
__device__ float  g_A[(size_t)MAXN * 320];    // layer-3 gather out (fp32)
__device__ __half g_WT1[1280 * 1280];
__device__ __half g_WT2[640 * 1280];
__device__ __half g_WT3[320 * 640];
__device__ float g_dis[MAXN];
__device__ int   g_deg[MAXN];
__device__ int   g_rowptr[MAXN + 1];
__device__ int   g_cursor[MAXN];
__device__ int   g_col[MAXE];

// ===================== helpers =====================
__device__ __forceinline__ void mma_f16(float* d, const uint32_t* a, const uint32_t* b) {
    asm volatile(
        "mma.sync.aligned.m16n8k16.row.col.f32.f16.f16.f32 "
        "{%0,%1,%2,%3}, {%4,%5,%6,%7}, {%8,%9}, {%0,%1,%2,%3};\n"
        : "+f"(d[0]), "+f"(d[1]), "+f"(d[2]), "+f"(d[3])
        : "r"(a[0]), "r"(a[1]), "r"(a[2]), "r"(a[3]), "r"(b[0]), "r"(b[1]));
}
__device__ __forceinline__ uint32_t smem_u32(const void* p) {
    uint32_t a;
    asm("{ .reg .u64 t; cvta.to.shared.u64 t, %1; cvt.u32.u64 %0, t; }" : "=r"(a) : "l"(p));
    return a;
}

// ===================== degree / normalization =====================
__global__ void k_init_deg(int* deg, int n) {
    int i = blockIdx.x * blockDim.x + threadIdx.x;
    if (i < n) deg[i] = 1;
}
__global__ void k_count_deg(const int* __restrict__ dst, int* deg, int e) {
    int i = blockIdx.x * blockDim.x + threadIdx.x;
    if (i < e) atomicAdd(&deg[dst[i]], 1);
}

// ===================== CSR build =====================
#define SCHUNK 20
__global__ void __launch_bounds__(1024)
k_scan(const int* __restrict__ deg, int* __restrict__ rowptr,
       int* __restrict__ cursor, float* __restrict__ dis, int n) {
    __shared__ int warpsum[32];
    const int tid = threadIdx.x;
    const int lane = tid & 31, wid = tid >> 5;
    const int chunk = (n + 1023) / 1024;
    const int start = tid * chunk;
    const int end = (start + chunk < n) ? start + chunk : n;
    const bool full20 = (chunk == SCHUNK) && (start + SCHUNK <= n);
    int dcache[SCHUNK];
    int cnt = end > start ? end - start : 0;
    if (full20) {
        const int4* dp = (const int4*)(deg + start);
#pragma unroll
        for (int q = 0; q < 5; q++) {
            int4 v4 = dp[q];
            dcache[q * 4 + 0] = v4.x;
            dcache[q * 4 + 1] = v4.y;
            dcache[q * 4 + 2] = v4.z;
            dcache[q * 4 + 3] = v4.w;
        }
        cnt = SCHUNK;
    } else {
        for (int i = 0; i < cnt; i++) dcache[i] = deg[start + i];
    }
    int s = 0;
    for (int i = 0; i < cnt; i++) s += dcache[i];
    int v = s;
#pragma unroll
    for (int o = 1; o < 32; o <<= 1) {
        int u = __shfl_up_sync(0xFFFFFFFFu, v, o);
        if (lane >= o) v += u;
    }
    if (lane == 31) warpsum[wid] = v;
    __syncthreads();
    if (wid == 0) {
        int w = warpsum[lane];
#pragma unroll
        for (int o = 1; o < 32; o <<= 1) {
            int u = __shfl_up_sync(0xFFFFFFFFu, w, o);
            if (lane >= o) w += u;
        }
        warpsum[lane] = w;
    }
    __syncthreads();
    int incl = v + (wid ? warpsum[wid - 1] : 0);
    int run = incl - s;
    int rp[SCHUNK];
    float dd[SCHUNK];
    for (int i = 0; i < cnt; i++) {
        rp[i] = run;
        dd[i] = rsqrtf((float)dcache[i]);
        run += dcache[i];
    }
    if (full20) {
        int4* rpp = (int4*)(rowptr + start);
        int4* cup = (int4*)(cursor + start);
        float4* dip = (float4*)(dis + start);
#pragma unroll
        for (int q = 0; q < 5; q++) {
            int4 rv = make_int4(rp[q * 4], rp[q * 4 + 1], rp[q * 4 + 2], rp[q * 4 + 3]);
            rpp[q] = rv;
            cup[q] = rv;
            dip[q] = make_float4(dd[q * 4], dd[q * 4 + 1], dd[q * 4 + 2], dd[q * 4 + 3]);
        }
    } else {
        for (int i = 0; i < cnt; i++) {
            rowptr[start + i] = rp[i];
            cursor[start + i] = rp[i];
            dis[start + i] = dd[i];
        }
    }
    if (start < n && end == n) rowptr[n] = run;
}

__global__ void k_fill(const int* __restrict__ src, const int* __restrict__ dst,
                       int* cursor, int* __restrict__ col, int e, int n) {
    int i = blockIdx.x * blockDim.x + threadIdx.x;
    if (i < e) {
        int pos = atomicAdd(&cursor[dst[i]], 1);
        col[pos] = src[i];
    } else if (i < e + n) {
        int j = i - e;
        int pos = atomicAdd(&cursor[j], 1);
        col[pos] = j;
    }
}

// ===================== conversions (k-pair-permuted fp16 output) ============
// Per 16-value k-group, pair p (=2 fp16) moves to word position:
//   p<4 -> 2p ; p>=4 -> 2(p-4)+1     (order [0,4,1,5,2,6,3,7])
__global__ void k_f2h(const float* __restrict__ in, __half* __restrict__ out, size_t n16) {
    size_t i = (size_t)blockIdx.x * blockDim.x + threadIdx.x;
    if (i < n16) {
        const float* ip = in + i * 16;
        float f[16];
#pragma unroll
        for (int q = 0; q < 4; q++) {
            float4 v = *(const float4*)(ip + q * 4);
            f[q * 4] = v.x; f[q * 4 + 1] = v.y; f[q * 4 + 2] = v.z; f[q * 4 + 3] = v.w;
        }
        __half2 w[8];
#pragma unroll
        for (int j = 0; j < 4; j++) {
            w[2 * j]     = __floats2half2_rn(f[2 * j],     f[2 * j + 1]);      // pair j
            w[2 * j + 1] = __floats2half2_rn(f[2 * j + 8], f[2 * j + 9]);      // pair j+4
        }
        uint4* op = (uint4*)(out + i * 16);
        op[0] = make_uint4(*(uint32_t*)&w[0], *(uint32_t*)&w[1],
                           *(uint32_t*)&w[2], *(uint32_t*)&w[3]);
        op[1] = make_uint4(*(uint32_t*)&w[4], *(uint32_t*)&w[5],
                           *(uint32_t*)&w[6], *(uint32_t*)&w[7]);
    }
}

// WT[m][kperm] = fp16(W[k][m]); fp16-pairs permuted within 16-k groups
__global__ void k_wt(const float* __restrict__ W, __half* __restrict__ WT,
                     int K, int M) {
    __shared__ float t[32][33];
    int k0 = blockIdx.y * 32, m0 = blockIdx.x * 32;
    int tx = threadIdx.x, ty = threadIdx.y;
#pragma unroll
    for (int i = ty; i < 32; i += 8)
        t[i][tx] = W[(size_t)(k0 + i) * M + m0 + tx];
    __syncthreads();
    int kk = tx & 15, grp = tx >> 4;
    int p = kk >> 1, j = kk & 1;
    int pos = (p < 4) ? 2 * p : 2 * (p - 4) + 1;
    int pk = (grp << 4) + pos * 2 + j;
#pragma unroll
    for (int i = ty; i < 32; i += 8)
        WT[(size_t)(m0 + i) * K + k0 + pk] = __float2half_rn(t[tx][i]);
}

// ===================== fp16 tensor-core GEMM (cp.async, 4-stage) ============
// Hb[N, M] = bf16( (Ah[N,K] @ WT[M,K]^T) * dis[row] )   fp32 accumulate
// Block 128x128, BK=32, 8 warps (2x4), warp tile 64x32, mma m16n8k16.
// SMEM rows: 24 words (16 data = 32 fp16 + 8 pad) -> conflict-free LDS.64.
#define GW 24
#define AW (128 * GW)
#define STAGE_WORDS (AW * 2)
#define NSTAGE 4

__global__ void __launch_bounds__(256, 2)
k_gemm_h(const __half* __restrict__ Ah, const __half* __restrict__ WT,
         __nv_bfloat16* __restrict__ C, const float* __restrict__ dis,
         int N, int K, int M) {
    extern __shared__ uint32_t smem[];
    const uint32_t sbase0 = smem_u32(smem);
    const int tid = threadIdx.x;
    const int wid = tid >> 5;
    const int lid = tid & 31;
    const int g4  = lid >> 2;
    const int tg  = lid & 3;
    const int wm  = wid >> 2;
    const int wn  = wid & 3;
    const int row0 = blockIdx.y * 128;
    const int col0 = blockIdx.x * 128;
    const int nk = K >> 5;             // BK = 32

    float acc[4][4][4];
#pragma unroll
    for (int i = 0; i < 4; i++)
#pragma unroll
        for (int j = 0; j < 4; j++)
#pragma unroll
            for (int k = 0; k < 4; k++) acc[i][j][k] = 0.0f;

    auto load_stage = [&](int s, int kt) {
        const int k0 = kt << 5;
        const uint32_t sb = sbase0 + (uint32_t)s * STAGE_WORDS * 4;
        // A: 128 rows x 32 fp16 (64B) = 512 x 16B chunks; 2 per thread
#pragma unroll
        for (int i = 0; i < 2; i++) {
            int c = tid + i * 256;
            int row = c >> 2, off = c & 3;
            int gr = row0 + row;
            int grc = gr < N ? gr : N - 1;
            const __half* src = Ah + (size_t)grc * K + k0 + off * 8;
            uint32_t dst = sb + (uint32_t)(row * GW + off * 4) * 4;
            int sz = (gr < N) ? 16 : 0;
            asm volatile("cp.async.cg.shared.global [%0], [%1], 16, %2;"
                         :: "r"(dst), "l"(src), "r"(sz));
        }
        // B: 128 n-rows x 32 fp16
#pragma unroll
        for (int i = 0; i < 2; i++) {
            int c = tid + i * 256;
            int n = c >> 2, off = c & 3;
            int gc = col0 + n;
            int gcc = gc < M ? gc : M - 1;
            const __half* src = WT + (size_t)gcc * K + k0 + off * 8;
            uint32_t dst = sb + (uint32_t)(AW + n * GW + off * 4) * 4;
            int sz = (gc < M) ? 16 : 0;
            asm volatile("cp.async.cg.shared.global [%0], [%1], 16, %2;"
                         :: "r"(dst), "l"(src), "r"(sz));
        }
        asm volatile("cp.async.commit_group;" ::: "memory");
    };

    for (int s = 0; s < NSTAGE - 1 && s < nk; s++) load_stage(s, s);

    for (int t = 0; t < nk; t++) {
        if (t + NSTAGE - 1 <= nk)
            asm volatile("cp.async.wait_group %0;" :: "n"(NSTAGE - 2) : "memory");
        else
            asm volatile("cp.async.wait_group 0;" ::: "memory");
        __syncthreads();
        if (t + NSTAGE - 1 < nk) load_stage((t + NSTAGE - 1) % NSTAGE, t + NSTAGE - 1);

        const uint32_t* as = smem + ((t % NSTAGE) * STAGE_WORDS);
        const uint32_t* bs = as + AW;
#pragma unroll
        for (int s = 0; s < 2; s++) {           // two k16 groups per BK=32
            const int kw = s * 8;               // 8 words per 16-k group
            uint32_t af[4][4], bf[4][2];
            // permuted layout: words (2tg, 2tg+1) = pairs (k=2tg..2tg+1, k=2tg+8..2tg+9)
#pragma unroll
            for (int mi = 0; mi < 4; mi++) {
                int r = wm * 64 + mi * 16 + g4;
                uint2 lo = *(const uint2*)(as + r * GW + kw + tg * 2);
                uint2 hi = *(const uint2*)(as + (r + 8) * GW + kw + tg * 2);
                af[mi][0] = lo.x;   // row r,   k=2tg..2tg+1
                af[mi][2] = lo.y;   // row r,   k=2tg+8..2tg+9
                af[mi][1] = hi.x;   // row r+8, k=2tg..2tg+1
                af[mi][3] = hi.y;   // row r+8, k=2tg+8..2tg+9
            }
#pragma unroll
            for (int nf = 0; nf < 4; nf++) {
                int cc = wn * 32 + nf * 8 + g4;
                uint2 bv = *(const uint2*)(bs + cc * GW + kw + tg * 2);
                bf[nf][0] = bv.x;   // k=2tg..2tg+1
                bf[nf][1] = bv.y;   // k=2tg+8..2tg+9
            }
#pragma unroll
            for (int mi = 0; mi < 4; mi++)
#pragma unroll
                for (int nf = 0; nf < 4; nf++)
                    mma_f16(acc[mi][nf], af[mi], bf[nf]);
        }
    }

    // epilogue: scale rows by dis[row], store bf16x2
#pragma unroll
    for (int mi = 0; mi < 4; mi++) {
        int r0 = row0 + wm * 64 + mi * 16 + g4;
        float d0 = (r0 < N) ? dis[r0] : 0.f;
        float d1 = (r0 + 8 < N) ? dis[r0 + 8] : 0.f;
#pragma unroll
        for (int nf = 0; nf < 4; nf++) {
            int cc = col0 + wn * 32 + nf * 8 + tg * 2;
            if (cc < M) {
                if (r0 < N)
                    *(__nv_bfloat162*)(C + (size_t)r0 * M + cc) =
                        __floats2bfloat162_rn(acc[mi][nf][0] * d0, acc[mi][nf][1] * d0);
                if (r0 + 8 < N)
                    *(__nv_bfloat162*)(C + (size_t)(r0 + 8) * M + cc) =
                        __floats2bfloat162_rn(acc[mi][nf][2] * d1, acc[mi][nf][3] * d1);
            }
        }
    }
}

// ===================== CSR gather (bf16 x8, 4-edge unroll) ===================
// outh!=null: store fp16 K-PAIR-PERMUTED (next GEMM input); else fp32 to outf.
__global__ void k_gather8(const __nv_bfloat16* __restrict__ H,
                          __half* __restrict__ outh, float* __restrict__ outf,
                          const int* __restrict__ rowptr, const int* __restrict__ col,
                          const float* __restrict__ dis, const float* __restrict__ b,
                          int M) {
    const int d = blockIdx.x;
    const int t = threadIdx.x;
    float acc[8];
#pragma unroll
    for (int i = 0; i < 8; i++) acc[i] = 0.f;
    const int beg = rowptr[d];
    const int end = rowptr[d + 1];
    int j = beg;
    for (; j + 3 < end; j += 4) {
        const int s0 = __ldg(&col[j]);
        const int s1 = __ldg(&col[j + 1]);
        const int s2 = __ldg(&col[j + 2]);
        const int s3 = __ldg(&col[j + 3]);
        uint4 u0 = __ldg((const uint4*)(H + (size_t)s0 * M) + t);
        uint4 u1 = __ldg((const uint4*)(H + (size_t)s1 * M) + t);
        uint4 u2 = __ldg((const uint4*)(H + (size_t)s2 * M) + t);
        uint4 u3 = __ldg((const uint4*)(H + (size_t)s3 * M) + t);
        const uint32_t* p0 = &u0.x;
        const uint32_t* p1 = &u1.x;
        const uint32_t* p2 = &u2.x;
        const uint32_t* p3 = &u3.x;
#pragma unroll
        for (int q = 0; q < 4; q++) {
            float2 f0 = __bfloat1622float2(*(const __nv_bfloat162*)&p0[q]);
            float2 f1 = __bfloat1622float2(*(const __nv_bfloat162*)&p1[q]);
            float2 f2 = __bfloat1622float2(*(const __nv_bfloat162*)&p2[q]);
            float2 f3 = __bfloat1622float2(*(const __nv_bfloat162*)&p3[q]);
            acc[q * 2]     += (f0.x + f1.x) + (f2.x + f3.x);
            acc[q * 2 + 1] += (f0.y + f1.y) + (f2.y + f3.y);
        }
    }
    for (; j < end; j++) {
        const int s0 = __ldg(&col[j]);
        uint4 u0 = __ldg((const uint4*)(H + (size_t)s0 * M) + t);
        const uint32_t* p0 = &u0.x;
#pragma unroll
        for (int q = 0; q < 4; q++) {
            float2 f0 = __bfloat1622float2(*(const __nv_bfloat162*)&p0[q]);
            acc[q * 2]     += f0.x;
            acc[q * 2 + 1] += f0.y;
        }
    }
    const float wd = dis[d];
    float4 b0 = __ldg((const float4*)(b) + t * 2);
    float4 b1 = __ldg((const float4*)(b) + t * 2 + 1);
    float r[8];
    r[0] = fmaxf(acc[0] * wd + b0.x, 0.f);
    r[1] = fmaxf(acc[1] * wd + b0.y, 0.f);
    r[2] = fmaxf(acc[2] * wd + b0.z, 0.f);
    r[3] = fmaxf(acc[3] * wd + b0.w, 0.f);
    r[4] = fmaxf(acc[4] * wd + b1.x, 0.f);
    r[5] = fmaxf(acc[5] * wd + b1.y, 0.f);
    r[6] = fmaxf(acc[6] * wd + b1.z, 0.f);
    r[7] = fmaxf(acc[7] * wd + b1.w, 0.f);
    if (outh) {
        // thread covers features [8t, 8t+8) = global pairs 4t..4t+3;
        // group g = t>>1; t even -> pairs 0..3 of group (pos 0,2,4,6),
        // t odd -> pairs 4..7 (pos 1,3,5,7). 1 pair = 1 u32 word.
        uint32_t* og = (uint32_t*)(outh + (size_t)d * M + (t >> 1) * 16);
        int o = t & 1;
#pragma unroll
        for (int q = 0; q < 4; q++) {
            __half2 h = __floats2half2_rn(r[2 * q], r[2 * q + 1]);
            og[2 * q + o] = *(uint32_t*)&h;
        }
    } else {
        float4* od = (float4*)(outf + (size_t)d * M) + t * 2;
        od[0] = make_float4(r[0], r[1], r[2], r[3]);
        od[1] = make_float4(r[4], r[5], r[6], r[7]);
    }
}

// ===================== fused mean-pool + MLP head ===========================
__global__ void __launch_bounds__(512)
k_head(const float* __restrict__ A, const int* __restrict__ batch,
       const float* __restrict__ fp_x,
       const float* __restrict__ Wg1, const float* __restrict__ bg1,
       const float* __restrict__ Wg2, const float* __restrict__ bg2,
       const float* __restrict__ Wf1, const float* __restrict__ bf1,
       const float* __restrict__ Wf2, const float* __restrict__ bf2,
       const float* __restrict__ Wo, const float* __restrict__ bo,
       float* __restrict__ out, int N) {
    __shared__ float xt[320];
    __shared__ float mc[193];
    __shared__ float m1[1024];
    __shared__ float m3[1024];
    __shared__ float m4[512];
    __shared__ float p2[4][128];
    __shared__ float red[16];
    const int g = blockIdx.x;
    const int tid = threadIdx.x;

    int lo = 0, hi = N;
    while (lo < hi) { int mid = (lo + hi) >> 1; if (batch[mid] < g) lo = mid + 1; else hi = mid; }
    const int beg = lo;
    hi = N;
    while (lo < hi) { int mid = (lo + hi) >> 1; if (batch[mid] < g + 1) lo = mid + 1; else hi = mid; }
    const int end = lo;
    if (tid < 320) {
        float s = 0.f;
        for (int i = beg; i < end; i++) s += A[(size_t)i * 320 + tid];
        xt[tid] = s / fmaxf((float)(end - beg), 1.0f);
    }
    __syncthreads();

    for (int m = tid; m < 1024; m += 512) {
        float acc = bg1[m];
        for (int k = 0; k < 320; k++) acc += xt[k] * Wg1[(size_t)k * 1024 + m];
        m1[m] = fmaxf(acc, 0.f);
    }
    __syncthreads();

    {
        int m = tid & 127, q = tid >> 7;
        float acc = 0.f;
        for (int k = q * 256; k < (q + 1) * 256; k++) acc += m1[k] * Wg2[(size_t)k * 128 + m];
        p2[q][m] = acc;
    }
    __syncthreads();
    if (tid < 128) mc[65 + tid] = bg2[tid] + p2[0][tid] + p2[1][tid] + p2[2][tid] + p2[3][tid];
    else if (tid < 128 + 65) mc[tid - 128] = fp_x[g * 65 + (tid - 128)];
    __syncthreads();

    for (int m = tid; m < 1024; m += 512) {
        float acc = bf1[m];
        for (int k = 0; k < 193; k++) acc += mc[k] * Wf1[(size_t)k * 1024 + m];
        m3[m] = fmaxf(acc, 0.f);
    }
    __syncthreads();

    {
        float acc = bf2[tid];
        for (int k = 0; k < 1024; k++) acc += m3[k] * Wf2[(size_t)k * 512 + tid];
        m4[tid] = fmaxf(acc, 0.f);
    }
    __syncthreads();

    float acc = m4[tid] * Wo[tid];
#pragma unroll
    for (int o = 16; o; o >>= 1) acc += __shfl_down_sync(0xFFFFFFFFu, acc, o);
    if ((tid & 31) == 0) red[tid >> 5] = acc;
    __syncthreads();
    if (tid < 16) {
        float v = red[tid];
#pragma unroll
        for (int o = 8; o; o >>= 1) v += __shfl_down_sync(0xFFFFu, v, o);
        if (tid == 0) out[g] = v + bo[0];
    }
}

// ===================== launch =====================
extern "C" void kernel_launch(void* const* d_in, const int* in_sizes, int n_in,
                              void* d_out, int out_size) {
    const float* x     = (const float*)d_in[0];
    const int*   ei    = (const int*)d_in[1];
    const int*   batch = (const int*)d_in[2];
    const float* fp_x  = (const float*)d_in[3];
    const float* W1 = (const float*)d_in[4];   const float* b1 = (const float*)d_in[5];
    const float* W2 = (const float*)d_in[6];   const float* b2 = (const float*)d_in[7];
    const float* W3 = (const float*)d_in[8];   const float* b3 = (const float*)d_in[9];
    const float* Wg1 = (const float*)d_in[10]; const float* bg1 = (const float*)d_in[11];
    const float* Wg2 = (const float*)d_in[12]; const float* bg2 = (const float*)d_in[13];
    const float* Wf1 = (const float*)d_in[14]; const float* bf1 = (const float*)d_in[15];
    const float* Wf2 = (const float*)d_in[16]; const float* bf2 = (const float*)d_in[17];
    const float* Wo  = (const float*)d_in[18]; const float* bo  = (const float*)d_in[19];

    const int N = in_sizes[0] / 1280;
    const int E = in_sizes[1] / 2;
    const int G = in_sizes[3] / 65;
    const int* srcp = ei;
    const int* dstp = ei + E;

    float *pA, *pdis;
    __half *pX, *pWT1, *pWT2, *pWT3;
    __nv_bfloat16* pHb;
    int *pdeg, *prowptr, *pcursor, *pcol;
    cudaGetSymbolAddress((void**)&pHb, g_Hb);
    cudaGetSymbolAddress((void**)&pX, g_X);
    cudaGetSymbolAddress((void**)&pA, g_A);
    cudaGetSymbolAddress((void**)&pWT1, g_WT1);
    cudaGetSymbolAddress((void**)&pWT2, g_WT2);
    cudaGetSymbolAddress((void**)&pWT3, g_WT3);
    cudaGetSymbolAddress((void**)&pdis, g_dis);
    cudaGetSymbolAddress((void**)&pdeg, g_deg);
    cudaGetSymbolAddress((void**)&prowptr, g_rowptr);
    cudaGetSymbolAddress((void**)&pcursor, g_cursor);
    cudaGetSymbolAddress((void**)&pcol, g_col);

    cudaFuncSetAttribute(k_gemm_h, cudaFuncAttributeMaxDynamicSharedMemorySize,
                         NSTAGE * STAGE_WORDS * 4);

    // side stream for CSR build (fork/join; capture-legal)
    cudaStream_t s1;
    cudaStreamCreateWithFlags(&s1, cudaStreamNonBlocking);
    cudaEvent_t evFork, evDis, evCsr;
    cudaEventCreateWithFlags(&evFork, cudaEventDisableTiming);
    cudaEventCreateWithFlags(&evDis, cudaEventDisableTiming);
    cudaEventCreateWithFlags(&evCsr, cudaEventDisableTiming);

    cudaEventRecord(evFork, 0);
    cudaStreamWaitEvent(s1, evFork, 0);

    // s1: CSR build; dis ready after k_scan; col/WT2/WT3 finish under GEMM1
    k_init_deg<<<(N + 255) / 256, 256, 0, s1>>>(pdeg, N);
    k_count_deg<<<(E + 255) / 256, 256, 0, s1>>>(dstp, pdeg, E);
    k_scan<<<1, 1024, 0, s1>>>(pdeg, prowptr, pcursor, pdis, N);
    cudaEventRecord(evDis, s1);
    k_fill<<<(E + N + 255) / 256, 256, 0, s1>>>(srcp, dstp, pcursor, pcol, E, N);
    {
        dim3 bt(32, 8);
        k_wt<<<dim3(640 / 32, 1280 / 32), bt, 0, s1>>>(W2, pWT2, 1280, 640);
        k_wt<<<dim3(320 / 32, 640 / 32), bt, 0, s1>>>(W3, pWT3, 640, 320);
    }
    cudaEventRecord(evCsr, s1);

    // default: conversions needed for GEMM1
    {
        size_t n16 = (size_t)N * 1280 / 16;
        k_f2h<<<(unsigned)((n16 + 255) / 256), 256>>>(x, pX, n16);
        dim3 bt(32, 8);
        k_wt<<<dim3(1280 / 32, 1280 / 32), bt>>>(W1, pWT1, 1280, 1280);
    }

    const unsigned smem_bytes = NSTAGE * STAGE_WORDS * 4;
    auto gemm = [&](const __half* in, const __half* WT, int K, int M) {
        dim3 gg((M + 127) / 128, (N + 127) / 128);
        k_gemm_h<<<gg, 256, smem_bytes>>>(in, WT, pHb, pdis, N, K, M);
    };

    // layer 1 (GEMM1 needs dis; gather needs full CSR)
    cudaStreamWaitEvent(0, evDis, 0);
    gemm(pX, pWT1, 1280, 1280);
    cudaStreamWaitEvent(0, evCsr, 0);
    k_gather8<<<N, 160>>>(pHb, pX, nullptr, prowptr, pcol, pdis, b1, 1280);
    // layer 2
    gemm(pX, pWT2, 1280, 640);
    k_gather8<<<N, 80>>>(pHb, pX, nullptr, prowptr, pcol, pdis, b2, 640);
    // layer 3
    gemm(pX, pWT3, 640, 320);
    k_gather8<<<N, 40>>>(pHb, nullptr, pA, prowptr, pcol, pdis, b3, 320);

    // fused mean-pool + MLP head
    k_head<<<G, 512>>>(pA, batch, fp_x, Wg1, bg1, Wg2, bg2,
                       Wf1, bf1, Wf2, bf2, Wo, bo, (float*)d_out, N);

    cudaEventDestroy(evFork);
    cudaEventDestroy(evDis);
    cudaEventDestroy(evCsr);
    cudaStreamDestroy(s1);
}